// round 1
// baseline (speedup 1.0000x reference)
#include <cuda_runtime.h>
#include <cuda_bf16.h>

#define N_   20000
#define E_   320000
#define B_   128
#define L_   2
#define SLOPE 0.2f
#define EPS_  1e-5f

// ---------------- scratch (static device allocations) ----------------
__device__ int   g_counts[N_];
__device__ int   g_rowptr[N_ + 1];
__device__ int   g_cursor[N_];
__device__ int   g_csr_src[E_];
__device__ int   g_perm[E_];

__device__ float g_wla[L_][128][2];   // collapsed W_l * att_l
__device__ float g_wlb[L_][128][2];   // collapsed W_l * att_r
__device__ float g_wea[L_][128][2];   // collapsed W_e * att_e
__device__ float g_insl[L_][B_][2];   // ins part of al per graph
__device__ float g_insr[L_][B_][2];
__device__ float g_inse[L_][B_][2];

__device__ float g_ae[L_][E_][2];     // edge attention term, CSR-permuted
__device__ float g_xl[(size_t)N_ * 128];
__device__ float g_alr[N_ * 4];       // al0, al1, ar0, ar1
__device__ float g_h[(size_t)N_ * 64];
__device__ float g_bnstats[128];      // sum[64], sumsq[64]

// ---------------- small utility kernels ----------------
__global__ void zero_kernel() {
    int i = blockIdx.x * blockDim.x + threadIdx.x;
    if (i < N_) g_counts[i] = 0;
    if (i < 128) g_bnstats[i] = 0.f;
}

__global__ void hist_kernel(const int* __restrict__ dst) {
    int i = blockIdx.x * blockDim.x + threadIdx.x;
    if (i < E_) atomicAdd(&g_counts[dst[i]], 1);
}

__global__ void scan_kernel() {
    __shared__ int sh[1024];
    int tid = threadIdx.x;
    int carry = 0;
    if (tid == 0) g_rowptr[0] = 0;
    for (int base = 0; base < N_; base += 1024) {
        int idx = base + tid;
        int v = (idx < N_) ? g_counts[idx] : 0;
        sh[tid] = v;
        __syncthreads();
        for (int o = 1; o < 1024; o <<= 1) {
            int t = (tid >= o) ? sh[tid - o] : 0;
            __syncthreads();
            sh[tid] += t;
            __syncthreads();
        }
        if (idx < N_) {
            g_rowptr[idx + 1] = carry + sh[tid];
            g_cursor[idx]     = carry + sh[tid] - v;
        }
        carry += sh[1023];
        __syncthreads();
    }
}

__global__ void scatter_kernel(const int* __restrict__ src, const int* __restrict__ dst) {
    int i = blockIdx.x * blockDim.x + threadIdx.x;
    if (i < E_) {
        int d = dst[i];
        int pos = atomicAdd(&g_cursor[d], 1);
        g_csr_src[pos] = src[i];
        g_perm[i] = pos;
    }
}

// collapse W (*) att -> 128x2 per layer for wla/wlb/wea
__global__ void collapse_kernel(const float* __restrict__ W_l,
                                const float* __restrict__ W_e,
                                const float* __restrict__ att_l,
                                const float* __restrict__ att_r,
                                const float* __restrict__ att_e) {
    int idx = blockIdx.x * blockDim.x + threadIdx.x;
    if (idx >= 3 * L_ * 128 * 2) return;
    int which = idx / (L_ * 128 * 2);
    int rem   = idx % (L_ * 128 * 2);
    int l = rem / 256;
    int k = (rem / 2) % 128;
    int h = rem & 1;
    const float* W   = (which == 2) ? W_e : W_l;
    const float* att = (which == 0) ? att_l : (which == 1) ? att_r : att_e;
    float s = 0.f;
    const float* wrow = W + ((size_t)l * 128 + k) * 128 + h * 64;
    const float* arow = att + l * 128 + h * 64;
    #pragma unroll 8
    for (int c = 0; c < 64; c++) s += wrow[c] * arow[c];
    if (which == 0) g_wla[l][k][h] = s;
    else if (which == 1) g_wlb[l][k][h] = s;
    else g_wea[l][k][h] = s;
}

// per-graph ins dot products (the ins-half of x_cat / e_cat)
__global__ void insdot_kernel(const float* __restrict__ instr) {
    int idx = blockIdx.x * blockDim.x + threadIdx.x;
    if (idx >= 3 * L_ * B_ * 2) return;
    int which = idx / (L_ * B_ * 2);
    int rem   = idx % (L_ * B_ * 2);
    int l = rem / (B_ * 2);
    int b = (rem / 2) % B_;
    int h = rem & 1;
    const float* iv = instr + ((size_t)l * B_ + b) * 64;
    float s = 0.f;
    #pragma unroll 8
    for (int k = 0; k < 64; k++) {
        float w = (which == 0) ? g_wla[l][64 + k][h]
                : (which == 1) ? g_wlb[l][64 + k][h]
                :                g_wea[l][64 + k][h];
        s += iv[k] * w;
    }
    if (which == 0) g_insl[l][b][h] = s;
    else if (which == 1) g_insr[l][b][h] = s;
    else g_inse[l][b][h] = s;
}

// ae for both layers in one pass over edge_attr; one warp per edge
__global__ void ae_kernel(const float* __restrict__ edge_attr,
                          const int* __restrict__ srcv,
                          const int* __restrict__ batch) {
    __shared__ float swe[L_][64][2];
    int tid = threadIdx.x;
    if (tid < 256) {
        int l = tid >> 7, rem = tid & 127;
        int k = rem >> 1, h = rem & 1;
        swe[l][k][h] = g_wea[l][k][h];
    }
    __syncthreads();
    int warp = blockIdx.x * (blockDim.x >> 5) + (tid >> 5);
    int lane = tid & 31;
    if (warp >= E_) return;
    float2 ea = *(const float2*)(edge_attr + (size_t)warp * 64 + lane * 2);
    int k0 = lane * 2, k1 = k0 + 1;
    float p00 = ea.x * swe[0][k0][0] + ea.y * swe[0][k1][0];
    float p01 = ea.x * swe[0][k0][1] + ea.y * swe[0][k1][1];
    float p10 = ea.x * swe[1][k0][0] + ea.y * swe[1][k1][0];
    float p11 = ea.x * swe[1][k0][1] + ea.y * swe[1][k1][1];
    #pragma unroll
    for (int o = 16; o; o >>= 1) {
        p00 += __shfl_xor_sync(0xffffffffu, p00, o);
        p01 += __shfl_xor_sync(0xffffffffu, p01, o);
        p10 += __shfl_xor_sync(0xffffffffu, p10, o);
        p11 += __shfl_xor_sync(0xffffffffu, p11, o);
    }
    if (lane == 0) {
        int b = batch[srcv[warp]];
        int pos = g_perm[warp];
        g_ae[0][pos][0] = p00 + g_inse[0][b][0];
        g_ae[0][pos][1] = p01 + g_inse[0][b][1];
        g_ae[1][pos][0] = p10 + g_inse[1][b][0];
        g_ae[1][pos][1] = p11 + g_inse[1][b][1];
    }
}

// al/ar per node for one layer; one warp per node
__global__ void alr_kernel(const float* __restrict__ hin,
                           const int* __restrict__ batch, int layer) {
    int warp = blockIdx.x * (blockDim.x >> 5) + (threadIdx.x >> 5);
    int lane = threadIdx.x & 31;
    if (warp >= N_) return;
    const float* hr = hin + (size_t)warp * 64;
    float x0 = hr[lane], x1 = hr[lane + 32];
    float al0 = x0 * g_wla[layer][lane][0] + x1 * g_wla[layer][lane + 32][0];
    float al1 = x0 * g_wla[layer][lane][1] + x1 * g_wla[layer][lane + 32][1];
    float ar0 = x0 * g_wlb[layer][lane][0] + x1 * g_wlb[layer][lane + 32][0];
    float ar1 = x0 * g_wlb[layer][lane][1] + x1 * g_wlb[layer][lane + 32][1];
    #pragma unroll
    for (int o = 16; o; o >>= 1) {
        al0 += __shfl_xor_sync(0xffffffffu, al0, o);
        al1 += __shfl_xor_sync(0xffffffffu, al1, o);
        ar0 += __shfl_xor_sync(0xffffffffu, ar0, o);
        ar1 += __shfl_xor_sync(0xffffffffu, ar1, o);
    }
    if (lane == 0) {
        int b = batch[warp];
        g_alr[warp * 4 + 0] = al0 + g_insl[layer][b][0];
        g_alr[warp * 4 + 1] = al1 + g_insl[layer][b][1];
        g_alr[warp * 4 + 2] = ar0 + g_insr[layer][b][0];
        g_alr[warp * 4 + 3] = ar1 + g_insr[layer][b][1];
    }
}

// ---------------- xl GEMM: [N,128] = concat(h, ins[batch]) @ W_l ----------------
// tile 64 rows x 128 cols, K=128 resident, 256 threads, 8x4 per-thread tile
#define GEMM_SHM ((128 * 68 + 128 * 128) * 4)
__global__ void gemm_xl(const float* __restrict__ hin,
                        const float* __restrict__ Wl,
                        const float* __restrict__ ins,
                        const int* __restrict__ batch) {
    extern __shared__ float sh[];
    float* As = sh;                 // [128][68], k-major (transposed)
    float* Ws = sh + 128 * 68;      // [128][128], k-major
    __shared__ int sbatch[64];
    int tid = threadIdx.x;
    int node0 = blockIdx.x * 64;
    int rows = min(64, N_ - node0);
    if (tid < 64) sbatch[tid] = (tid < rows) ? batch[node0 + tid] : 0;
    const float4* Wg = (const float4*)Wl;
    float4* Ws4 = (float4*)Ws;
    for (int i = tid; i < 128 * 32; i += 256) Ws4[i] = Wg[i];
    __syncthreads();
    for (int i = tid; i < 64 * 128; i += 256) {
        int m = i >> 7, k = i & 127;
        float v = 0.f;
        if (m < rows) {
            v = (k < 64) ? hin[(size_t)(node0 + m) * 64 + k]
                         : ins[(size_t)sbatch[m] * 64 + (k - 64)];
        }
        As[k * 68 + m] = v;
    }
    __syncthreads();
    int rt = tid >> 5, lane = tid & 31;
    float acc[8][4];
    #pragma unroll
    for (int r = 0; r < 8; r++)
        #pragma unroll
        for (int j = 0; j < 4; j++) acc[r][j] = 0.f;
    #pragma unroll 4
    for (int k = 0; k < 128; k++) {
        const float* ar = As + k * 68 + rt * 8;
        float4 a0 = *(const float4*)ar;
        float4 a1 = *(const float4*)(ar + 4);
        float4 b  = *(const float4*)(Ws + k * 128 + lane * 4);
        float av[8] = {a0.x, a0.y, a0.z, a0.w, a1.x, a1.y, a1.z, a1.w};
        #pragma unroll
        for (int r = 0; r < 8; r++) {
            acc[r][0] += av[r] * b.x;
            acc[r][1] += av[r] * b.y;
            acc[r][2] += av[r] * b.z;
            acc[r][3] += av[r] * b.w;
        }
    }
    #pragma unroll
    for (int r = 0; r < 8; r++) {
        int m = rt * 8 + r;
        if (m < rows) {
            float4 v = {acc[r][0], acc[r][1], acc[r][2], acc[r][3]};
            *(float4*)(g_xl + (size_t)(node0 + m) * 128 + lane * 4) = v;
        }
    }
}

// ---------------- per-node softmax + aggregation; one warp per node ----------------
__global__ void agg_kernel(int layer, const float* __restrict__ hin,
                           float* __restrict__ hout,
                           const float* __restrict__ bias, int do_stats) {
    __shared__ float s_sum[64], s_sq[64];
    int tid = threadIdx.x;
    if (do_stats) {
        if (tid < 64) { s_sum[tid] = 0.f; s_sq[tid] = 0.f; }
        __syncthreads();
    }
    int node = blockIdx.x * 8 + (tid >> 5);
    int lane = tid & 31;
    if (node < N_) {
        int start = g_rowptr[node], end = g_rowptr[node + 1];
        const float2* aep = (const float2*)&g_ae[layer][0][0];
        float2 arr = *(const float2*)&g_alr[node * 4 + 2];
        float m0 = -1e30f, m1 = -1e30f;
        for (int p = start + lane; p < end; p += 32) {
            int s = g_csr_src[p];
            float2 al = *(const float2*)&g_alr[s * 4];
            float2 ae = aep[p];
            float a0 = al.x + arr.x + ae.x; a0 = fmaxf(a0, SLOPE * a0);
            float a1 = al.y + arr.y + ae.y; a1 = fmaxf(a1, SLOPE * a1);
            m0 = fmaxf(m0, a0); m1 = fmaxf(m1, a1);
        }
        #pragma unroll
        for (int o = 16; o; o >>= 1) {
            m0 = fmaxf(m0, __shfl_xor_sync(0xffffffffu, m0, o));
            m1 = fmaxf(m1, __shfl_xor_sync(0xffffffffu, m1, o));
        }
        float s0 = 0.f, s1 = 0.f;
        for (int p = start + lane; p < end; p += 32) {
            int s = g_csr_src[p];
            float2 al = *(const float2*)&g_alr[s * 4];
            float2 ae = aep[p];
            float a0 = al.x + arr.x + ae.x; a0 = fmaxf(a0, SLOPE * a0);
            float a1 = al.y + arr.y + ae.y; a1 = fmaxf(a1, SLOPE * a1);
            s0 += __expf(a0 - m0); s1 += __expf(a1 - m1);
        }
        #pragma unroll
        for (int o = 16; o; o >>= 1) {
            s0 += __shfl_xor_sync(0xffffffffu, s0, o);
            s1 += __shfl_xor_sync(0xffffffffu, s1, o);
        }
        float sc0 = 1.f / (s0 + 1e-16f), sc1 = 1.f / (s1 + 1e-16f);
        bool head1 = lane >= 16;
        float acc0 = 0.f, acc1 = 0.f, acc2 = 0.f, acc3 = 0.f;
        for (int p = start; p < end; p++) {
            int s = g_csr_src[p];                       // warp-uniform
            float2 al = *(const float2*)&g_alr[s * 4];
            float2 ae = aep[p];
            float a0 = al.x + arr.x + ae.x; a0 = fmaxf(a0, SLOPE * a0);
            float a1 = al.y + arr.y + ae.y; a1 = fmaxf(a1, SLOPE * a1);
            float w = __expf((head1 ? a1 : a0) - (head1 ? m1 : m0));
            float4 x = *(const float4*)(g_xl + (size_t)s * 128 + lane * 4);
            acc0 += w * x.x; acc1 += w * x.y; acc2 += w * x.z; acc3 += w * x.w;
        }
        float sc = head1 ? sc1 : sc0;
        float o0 = acc0 * sc, o1 = acc1 * sc, o2 = acc2 * sc, o3 = acc3 * sc;
        float p0 = __shfl_xor_sync(0xffffffffu, o0, 16);
        float p1 = __shfl_xor_sync(0xffffffffu, o1, 16);
        float p2 = __shfl_xor_sync(0xffffffffu, o2, 16);
        float p3 = __shfl_xor_sync(0xffffffffu, o3, 16);
        if (!head1) {
            int coff = lane * 4;
            float4 hv = *(const float4*)(hin + (size_t)node * 64 + coff);
            float4 bv = *(const float4*)(bias + layer * 64 + coff);
            float r0 = (o0 + p0) * 0.5f + bv.x + hv.x;
            float r1 = (o1 + p1) * 0.5f + bv.y + hv.y;
            float r2 = (o2 + p2) * 0.5f + bv.z + hv.z;
            float r3 = (o3 + p3) * 0.5f + bv.w + hv.w;
            float4 res = {r0, r1, r2, r3};
            *(float4*)(hout + (size_t)node * 64 + coff) = res;
            if (do_stats) {
                atomicAdd(&s_sum[coff + 0], r0); atomicAdd(&s_sq[coff + 0], r0 * r0);
                atomicAdd(&s_sum[coff + 1], r1); atomicAdd(&s_sq[coff + 1], r1 * r1);
                atomicAdd(&s_sum[coff + 2], r2); atomicAdd(&s_sq[coff + 2], r2 * r2);
                atomicAdd(&s_sum[coff + 3], r3); atomicAdd(&s_sq[coff + 3], r3 * r3);
            }
        }
    }
    if (do_stats) {
        __syncthreads();
        if (tid < 64) {
            atomicAdd(&g_bnstats[tid],      s_sum[tid]);
            atomicAdd(&g_bnstats[64 + tid], s_sq[tid]);
        }
    }
}

__global__ void bn_norm_kernel(float* __restrict__ h,
                               const float* __restrict__ gamma,
                               const float* __restrict__ beta) {
    int i = blockIdx.x * blockDim.x + threadIdx.x;
    if (i >= N_ * 64) return;
    int c = i & 63;
    float mu  = g_bnstats[c] * (1.f / N_);
    float var = g_bnstats[64 + c] * (1.f / N_) - mu * mu;
    float inv = rsqrtf(var + EPS_);
    float v = (h[i] - mu) * inv * gamma[c] + beta[c];
    h[i] = v > 0.f ? v : 0.f;
}

// ---------------- launch ----------------
extern "C" void kernel_launch(void* const* d_in, const int* in_sizes, int n_in,
                              void* d_out, int out_size) {
    const float* x         = (const float*)d_in[0];
    const int*   eidx      = (const int*)d_in[1];
    const float* edge_attr = (const float*)d_in[2];
    const float* instr     = (const float*)d_in[3];
    const int*   batch     = (const int*)d_in[4];
    const float* W_l       = (const float*)d_in[5];
    const float* W_e       = (const float*)d_in[6];
    const float* att_l     = (const float*)d_in[7];
    const float* att_r     = (const float*)d_in[8];
    const float* att_e     = (const float*)d_in[9];
    const float* bias      = (const float*)d_in[10];
    const float* bn_gamma  = (const float*)d_in[11];
    const float* bn_beta   = (const float*)d_in[12];
    float* out = (float*)d_out;

    const int* src = eidx;
    const int* dst = eidx + E_;

    float* h_ptr = nullptr;
    cudaGetSymbolAddress((void**)&h_ptr, g_h);
    cudaFuncSetAttribute(gemm_xl, cudaFuncAttributeMaxDynamicSharedMemorySize, GEMM_SHM);

    zero_kernel<<<(N_ + 255) / 256, 256>>>();
    hist_kernel<<<(E_ + 255) / 256, 256>>>(dst);
    scan_kernel<<<1, 1024>>>();
    scatter_kernel<<<(E_ + 255) / 256, 256>>>(src, dst);
    collapse_kernel<<<6, 256>>>(W_l, W_e, att_l, att_r, att_e);
    insdot_kernel<<<6, 256>>>(instr);
    ae_kernel<<<(E_ + 7) / 8, 256>>>(edge_attr, src, batch);

    // layer 0 (input x, output g_h, collect BN stats)
    gemm_xl<<<(N_ + 63) / 64, 256, GEMM_SHM>>>(x, W_l, instr, batch);
    alr_kernel<<<(N_ + 7) / 8, 256>>>(x, batch, 0);
    agg_kernel<<<(N_ + 7) / 8, 256>>>(0, x, h_ptr, bias, 1);
    bn_norm_kernel<<<(N_ * 64 + 255) / 256, 256>>>(h_ptr, bn_gamma, bn_beta);

    // layer 1 (input g_h, output d_out)
    gemm_xl<<<(N_ + 63) / 64, 256, GEMM_SHM>>>(h_ptr, W_l + 128 * 128, instr + B_ * 64, batch);
    alr_kernel<<<(N_ + 7) / 8, 256>>>(h_ptr, batch, 1);
    agg_kernel<<<(N_ + 7) / 8, 256>>>(1, h_ptr, out, bias, 0);
}

// round 2
// speedup vs baseline: 1.0850x; 1.0850x over previous
#include <cuda_runtime.h>
#include <cuda_bf16.h>

#define N_   20000
#define E_   320000
#define B_   128
#define L_   2
#define SLOPE 0.2f
#define EPS_  1e-5f

// ---------------- scratch (static device allocations) ----------------
__device__ int   g_counts[N_];
__device__ int   g_rowptr[N_ + 1];
__device__ int   g_cursor[N_];
__device__ int   g_csr_src[E_];
__device__ int   g_perm[E_];

__device__ float g_wla[L_][128][2];   // collapsed W_l * att_l
__device__ float g_wlb[L_][128][2];   // collapsed W_l * att_r
__device__ float g_wea[L_][128][2];   // collapsed W_e * att_e
__device__ float g_insl[L_][B_][2];   // ins part of al per graph
__device__ float g_insr[L_][B_][2];
__device__ float g_inse[L_][B_][2];

__device__ float2 g_ae[L_][E_];       // edge attention term, CSR-permuted
__device__ float2 g_att[E_];          // per-layer scratch: post-leaky logits
__device__ float g_xl[(size_t)N_ * 128];
__device__ float g_alr[N_ * 4];       // al0, al1, ar0, ar1
__device__ float g_h[(size_t)N_ * 64];
__device__ float g_bnstats[128];      // sum[64], sumsq[64]

// ---------------- CSR build ----------------
__global__ void zero_kernel() {
    int i = blockIdx.x * blockDim.x + threadIdx.x;
    if (i < N_) g_counts[i] = 0;
    if (i < 128) g_bnstats[i] = 0.f;
}

__global__ void hist_kernel(const int* __restrict__ dst) {
    int i = blockIdx.x * blockDim.x + threadIdx.x;
    if (i < E_) atomicAdd(&g_counts[dst[i]], 1);
}

// single block, 1024 threads, 20 elems per thread (serial) + one block scan
__global__ void scan_kernel() {
    __shared__ int sums[1024];
    const int C = 20;                  // 1024*20 = 20480 >= N_
    int t = threadIdx.x;
    int base = t * C;
    int vals[C];
    int run = 0;
    #pragma unroll
    for (int i = 0; i < C; i++) {
        int idx = base + i;
        int v = (idx < N_) ? g_counts[idx] : 0;
        run += v;
        vals[i] = run;                 // thread-local inclusive
    }
    sums[t] = run;
    __syncthreads();
    for (int o = 1; o < 1024; o <<= 1) {
        int x = (t >= o) ? sums[t - o] : 0;
        __syncthreads();
        sums[t] += x;
        __syncthreads();
    }
    int off = sums[t] - run;           // exclusive prefix of this thread's chunk
    if (t == 0) g_rowptr[0] = 0;
    #pragma unroll
    for (int i = 0; i < C; i++) {
        int idx = base + i;
        if (idx < N_) {
            int incl = off + vals[i];
            int cnt  = vals[i] - (i ? vals[i - 1] : 0);
            g_rowptr[idx + 1] = incl;
            g_cursor[idx]     = incl - cnt;
        }
    }
}

__global__ void scatter_kernel(const int* __restrict__ src, const int* __restrict__ dst) {
    int i = blockIdx.x * blockDim.x + threadIdx.x;
    if (i < E_) {
        int d = dst[i];
        int pos = atomicAdd(&g_cursor[d], 1);
        g_csr_src[pos] = src[i];
        g_perm[i] = pos;
    }
}

// ---------------- merged setup: collapse W*att + ins dot products ----------------
__global__ void setup_kernel(const float* __restrict__ W_l,
                             const float* __restrict__ W_e,
                             const float* __restrict__ att_l,
                             const float* __restrict__ att_r,
                             const float* __restrict__ att_e,
                             const float* __restrict__ instr) {
    int tid = threadIdx.x;             // 512 threads, 1 block
    // phase 1: collapse -> g_wla / g_wlb / g_wea  (1536 outputs, 3 per thread)
    for (int idx = tid; idx < 3 * L_ * 128 * 2; idx += 512) {
        int which = idx / (L_ * 128 * 2);
        int rem   = idx % (L_ * 128 * 2);
        int l = rem / 256;
        int k = (rem / 2) % 128;
        int h = rem & 1;
        const float* W   = (which == 2) ? W_e : W_l;
        const float* att = (which == 0) ? att_l : (which == 1) ? att_r : att_e;
        const float* wrow = W + ((size_t)l * 128 + k) * 128 + h * 64;
        const float* arow = att + l * 128 + h * 64;
        float s = 0.f;
        #pragma unroll 8
        for (int c = 0; c < 64; c++) s += wrow[c] * arow[c];
        if (which == 0) g_wla[l][k][h] = s;
        else if (which == 1) g_wlb[l][k][h] = s;
        else g_wea[l][k][h] = s;
    }
    __syncthreads();
    // phase 2: ins dots (1536 outputs)
    for (int idx = tid; idx < 3 * L_ * B_ * 2; idx += 512) {
        int which = idx / (L_ * B_ * 2);
        int rem   = idx % (L_ * B_ * 2);
        int l = rem / (B_ * 2);
        int b = (rem / 2) % B_;
        int h = rem & 1;
        const float* iv = instr + ((size_t)l * B_ + b) * 64;
        float s = 0.f;
        #pragma unroll 8
        for (int k = 0; k < 64; k++) {
            float w = (which == 0) ? g_wla[l][64 + k][h]
                    : (which == 1) ? g_wlb[l][64 + k][h]
                    :                g_wea[l][64 + k][h];
            s += iv[k] * w;
        }
        if (which == 0) g_insl[l][b][h] = s;
        else if (which == 1) g_insr[l][b][h] = s;
        else g_inse[l][b][h] = s;
    }
}

// ---------------- ae: both layers, 4 edges per warp ----------------
__global__ void ae_kernel(const float* __restrict__ edge_attr,
                          const int* __restrict__ srcv,
                          const int* __restrict__ batch) {
    __shared__ float swe[L_][64][2];
    int tid = threadIdx.x;
    {
        int l = tid >> 7, rem = tid & 127;
        int k = rem >> 1, h = rem & 1;
        swe[l][k][h] = g_wea[l][k][h];
    }
    __syncthreads();
    int warp = blockIdx.x * 8 + (tid >> 5);
    int lane = tid & 31;
    int sub = lane >> 3, l8 = lane & 7;
    int e = warp * 4 + sub;
    if (e >= E_) return;
    const float* row = edge_attr + (size_t)e * 64;
    float4 v0 = *(const float4*)(row + l8 * 4);
    float4 v1 = *(const float4*)(row + 32 + l8 * 4);
    float vv[8] = {v0.x, v0.y, v0.z, v0.w, v1.x, v1.y, v1.z, v1.w};
    int k0 = l8 * 4;
    float acc[4] = {0.f, 0.f, 0.f, 0.f};
    #pragma unroll
    for (int j = 0; j < 8; j++) {
        int k = (j < 4) ? (k0 + j) : (32 + k0 + j - 4);
        #pragma unroll
        for (int l = 0; l < 2; l++)
            #pragma unroll
            for (int h = 0; h < 2; h++)
                acc[l * 2 + h] += vv[j] * swe[l][k][h];
    }
    #pragma unroll
    for (int o = 4; o; o >>= 1) {
        #pragma unroll
        for (int c = 0; c < 4; c++)
            acc[c] += __shfl_xor_sync(0xffffffffu, acc[c], o);
    }
    if (l8 == 0) {
        int b = batch[srcv[e]];
        int pos = g_perm[e];
        g_ae[0][pos] = make_float2(acc[0] + g_inse[0][b][0], acc[1] + g_inse[0][b][1]);
        g_ae[1][pos] = make_float2(acc[2] + g_inse[1][b][0], acc[3] + g_inse[1][b][1]);
    }
}

// ---------------- al/ar per node; one warp per node ----------------
__global__ void alr_kernel(const float* __restrict__ hin,
                           const int* __restrict__ batch, int layer) {
    int warp = blockIdx.x * (blockDim.x >> 5) + (threadIdx.x >> 5);
    int lane = threadIdx.x & 31;
    if (warp >= N_) return;
    const float* hr = hin + (size_t)warp * 64;
    float x0 = hr[lane], x1 = hr[lane + 32];
    float al0 = x0 * g_wla[layer][lane][0] + x1 * g_wla[layer][lane + 32][0];
    float al1 = x0 * g_wla[layer][lane][1] + x1 * g_wla[layer][lane + 32][1];
    float ar0 = x0 * g_wlb[layer][lane][0] + x1 * g_wlb[layer][lane + 32][0];
    float ar1 = x0 * g_wlb[layer][lane][1] + x1 * g_wlb[layer][lane + 32][1];
    #pragma unroll
    for (int o = 16; o; o >>= 1) {
        al0 += __shfl_xor_sync(0xffffffffu, al0, o);
        al1 += __shfl_xor_sync(0xffffffffu, al1, o);
        ar0 += __shfl_xor_sync(0xffffffffu, ar0, o);
        ar1 += __shfl_xor_sync(0xffffffffu, ar1, o);
    }
    if (lane == 0) {
        int b = batch[warp];
        g_alr[warp * 4 + 0] = al0 + g_insl[layer][b][0];
        g_alr[warp * 4 + 1] = al1 + g_insl[layer][b][1];
        g_alr[warp * 4 + 2] = ar0 + g_insr[layer][b][0];
        g_alr[warp * 4 + 3] = ar1 + g_insr[layer][b][1];
    }
}

// ---------------- xl GEMM (unchanged, verified) ----------------
#define GEMM_SHM ((128 * 68 + 128 * 128) * 4)
__global__ void gemm_xl(const float* __restrict__ hin,
                        const float* __restrict__ Wl,
                        const float* __restrict__ ins,
                        const int* __restrict__ batch) {
    extern __shared__ float sh[];
    float* As = sh;                 // [128][68], k-major (transposed)
    float* Ws = sh + 128 * 68;      // [128][128], k-major
    __shared__ int sbatch[64];
    int tid = threadIdx.x;
    int node0 = blockIdx.x * 64;
    int rows = min(64, N_ - node0);
    if (tid < 64) sbatch[tid] = (tid < rows) ? batch[node0 + tid] : 0;
    const float4* Wg = (const float4*)Wl;
    float4* Ws4 = (float4*)Ws;
    for (int i = tid; i < 128 * 32; i += 256) Ws4[i] = Wg[i];
    __syncthreads();
    for (int i = tid; i < 64 * 128; i += 256) {
        int m = i >> 7, k = i & 127;
        float v = 0.f;
        if (m < rows) {
            v = (k < 64) ? hin[(size_t)(node0 + m) * 64 + k]
                         : ins[(size_t)sbatch[m] * 64 + (k - 64)];
        }
        As[k * 68 + m] = v;
    }
    __syncthreads();
    int rt = tid >> 5, lane = tid & 31;
    float acc[8][4];
    #pragma unroll
    for (int r = 0; r < 8; r++)
        #pragma unroll
        for (int j = 0; j < 4; j++) acc[r][j] = 0.f;
    #pragma unroll 4
    for (int k = 0; k < 128; k++) {
        const float* ar = As + k * 68 + rt * 8;
        float4 a0 = *(const float4*)ar;
        float4 a1 = *(const float4*)(ar + 4);
        float4 b  = *(const float4*)(Ws + k * 128 + lane * 4);
        float av[8] = {a0.x, a0.y, a0.z, a0.w, a1.x, a1.y, a1.z, a1.w};
        #pragma unroll
        for (int r = 0; r < 8; r++) {
            acc[r][0] += av[r] * b.x;
            acc[r][1] += av[r] * b.y;
            acc[r][2] += av[r] * b.z;
            acc[r][3] += av[r] * b.w;
        }
    }
    #pragma unroll
    for (int r = 0; r < 8; r++) {
        int m = rt * 8 + r;
        if (m < rows) {
            float4 v = {acc[r][0], acc[r][1], acc[r][2], acc[r][3]};
            *(float4*)(g_xl + (size_t)(node0 + m) * 128 + lane * 4) = v;
        }
    }
}

// ---------------- per-node online softmax + aggregation; one warp per node ----------------
__global__ void agg_kernel(int layer, const float* __restrict__ hin,
                           float* __restrict__ hout,
                           const float* __restrict__ bias, int do_stats) {
    __shared__ float s_sum[64], s_sq[64];
    int tid = threadIdx.x;
    if (do_stats) {
        if (tid < 64) { s_sum[tid] = 0.f; s_sq[tid] = 0.f; }
        __syncthreads();
    }
    int node = blockIdx.x * 8 + (tid >> 5);
    int lane = tid & 31;
    if (node < N_) {
        int start = g_rowptr[node], end = g_rowptr[node + 1];
        const float2* aep = g_ae[layer];
        float2 arr = *(const float2*)&g_alr[node * 4 + 2];
        // pass A: online (max, sum) + store post-leaky logits
        float m0 = -1e30f, m1 = -1e30f, s0 = 0.f, s1 = 0.f;
        for (int p = start + lane; p < end; p += 32) {
            int s = g_csr_src[p];
            float2 al = *(const float2*)&g_alr[s * 4];
            float2 ae = aep[p];
            float a0 = al.x + arr.x + ae.x; a0 = fmaxf(a0, SLOPE * a0);
            float a1 = al.y + arr.y + ae.y; a1 = fmaxf(a1, SLOPE * a1);
            g_att[p] = make_float2(a0, a1);
            float nm0 = fmaxf(m0, a0);
            s0 = s0 * __expf(m0 - nm0) + __expf(a0 - nm0); m0 = nm0;
            float nm1 = fmaxf(m1, a1);
            s1 = s1 * __expf(m1 - nm1) + __expf(a1 - nm1); m1 = nm1;
        }
        #pragma unroll
        for (int o = 16; o; o >>= 1) {
            float om0 = __shfl_xor_sync(0xffffffffu, m0, o);
            float os0 = __shfl_xor_sync(0xffffffffu, s0, o);
            float nm0 = fmaxf(m0, om0);
            s0 = s0 * __expf(m0 - nm0) + os0 * __expf(om0 - nm0); m0 = nm0;
            float om1 = __shfl_xor_sync(0xffffffffu, m1, o);
            float os1 = __shfl_xor_sync(0xffffffffu, s1, o);
            float nm1 = fmaxf(m1, om1);
            s1 = s1 * __expf(m1 - nm1) + os1 * __expf(om1 - nm1); m1 = nm1;
        }
        float sc0 = 1.f / (s0 + 1e-16f), sc1 = 1.f / (s1 + 1e-16f);
        __threadfence_block();
        __syncwarp();
        // pass B: weighted aggregation reading coalesced logits
        bool head1 = lane >= 16;
        float mh = head1 ? m1 : m0;
        float acc0 = 0.f, acc1 = 0.f, acc2 = 0.f, acc3 = 0.f;
        #pragma unroll 2
        for (int p = start; p < end; p++) {
            int s = g_csr_src[p];                       // warp-uniform
            float2 a = g_att[p];
            float w = __expf((head1 ? a.y : a.x) - mh);
            float4 x = *(const float4*)(g_xl + (size_t)s * 128 + lane * 4);
            acc0 += w * x.x; acc1 += w * x.y; acc2 += w * x.z; acc3 += w * x.w;
        }
        float sc = head1 ? sc1 : sc0;
        float o0 = acc0 * sc, o1 = acc1 * sc, o2 = acc2 * sc, o3 = acc3 * sc;
        float p0 = __shfl_xor_sync(0xffffffffu, o0, 16);
        float p1 = __shfl_xor_sync(0xffffffffu, o1, 16);
        float p2 = __shfl_xor_sync(0xffffffffu, o2, 16);
        float p3 = __shfl_xor_sync(0xffffffffu, o3, 16);
        if (!head1) {
            int coff = lane * 4;
            float4 hv = *(const float4*)(hin + (size_t)node * 64 + coff);
            float4 bv = *(const float4*)(bias + layer * 64 + coff);
            float r0 = (o0 + p0) * 0.5f + bv.x + hv.x;
            float r1 = (o1 + p1) * 0.5f + bv.y + hv.y;
            float r2 = (o2 + p2) * 0.5f + bv.z + hv.z;
            float r3 = (o3 + p3) * 0.5f + bv.w + hv.w;
            float4 res = {r0, r1, r2, r3};
            *(float4*)(hout + (size_t)node * 64 + coff) = res;
            if (do_stats) {
                atomicAdd(&s_sum[coff + 0], r0); atomicAdd(&s_sq[coff + 0], r0 * r0);
                atomicAdd(&s_sum[coff + 1], r1); atomicAdd(&s_sq[coff + 1], r1 * r1);
                atomicAdd(&s_sum[coff + 2], r2); atomicAdd(&s_sq[coff + 2], r2 * r2);
                atomicAdd(&s_sum[coff + 3], r3); atomicAdd(&s_sq[coff + 3], r3 * r3);
            }
        }
    }
    if (do_stats) {
        __syncthreads();
        if (tid < 64) {
            atomicAdd(&g_bnstats[tid],      s_sum[tid]);
            atomicAdd(&g_bnstats[64 + tid], s_sq[tid]);
        }
    }
}

__global__ void bn_norm_kernel(float* __restrict__ h,
                               const float* __restrict__ gamma,
                               const float* __restrict__ beta) {
    int i = blockIdx.x * blockDim.x + threadIdx.x;
    if (i >= N_ * 64) return;
    int c = i & 63;
    float mu  = g_bnstats[c] * (1.f / N_);
    float var = g_bnstats[64 + c] * (1.f / N_) - mu * mu;
    float inv = rsqrtf(var + EPS_);
    float v = (h[i] - mu) * inv * gamma[c] + beta[c];
    h[i] = v > 0.f ? v : 0.f;
}

// ---------------- launch ----------------
extern "C" void kernel_launch(void* const* d_in, const int* in_sizes, int n_in,
                              void* d_out, int out_size) {
    const float* x         = (const float*)d_in[0];
    const int*   eidx      = (const int*)d_in[1];
    const float* edge_attr = (const float*)d_in[2];
    const float* instr     = (const float*)d_in[3];
    const int*   batch     = (const int*)d_in[4];
    const float* W_l       = (const float*)d_in[5];
    const float* W_e       = (const float*)d_in[6];
    const float* att_l     = (const float*)d_in[7];
    const float* att_r     = (const float*)d_in[8];
    const float* att_e     = (const float*)d_in[9];
    const float* bias      = (const float*)d_in[10];
    const float* bn_gamma  = (const float*)d_in[11];
    const float* bn_beta   = (const float*)d_in[12];
    float* out = (float*)d_out;

    const int* src = eidx;
    const int* dst = eidx + E_;

    float* h_ptr = nullptr;
    cudaGetSymbolAddress((void**)&h_ptr, g_h);
    cudaFuncSetAttribute(gemm_xl, cudaFuncAttributeMaxDynamicSharedMemorySize, GEMM_SHM);

    // fork-join: CSR build on a side stream, overlapped with setup + gemm0 + alr0
    cudaStream_t s2;
    cudaStreamCreateWithFlags(&s2, cudaStreamNonBlocking);
    cudaEvent_t e1, e2;
    cudaEventCreateWithFlags(&e1, cudaEventDisableTiming);
    cudaEventCreateWithFlags(&e2, cudaEventDisableTiming);

    cudaEventRecord(e1, 0);
    cudaStreamWaitEvent(s2, e1, 0);
    zero_kernel<<<(N_ + 255) / 256, 256, 0, s2>>>();
    hist_kernel<<<(E_ + 255) / 256, 256, 0, s2>>>(dst);
    scan_kernel<<<1, 1024, 0, s2>>>();
    scatter_kernel<<<(E_ + 255) / 256, 256, 0, s2>>>(src, dst);
    cudaEventRecord(e2, s2);

    // main stream: weight prep + layer-0 linear parts (independent of CSR)
    setup_kernel<<<1, 512>>>(W_l, W_e, att_l, att_r, att_e, instr);
    gemm_xl<<<(N_ + 63) / 64, 256, GEMM_SHM>>>(x, W_l, instr, batch);
    alr_kernel<<<(N_ + 7) / 8, 256>>>(x, batch, 0);

    cudaStreamWaitEvent(0, e2, 0);     // join CSR branch
    ae_kernel<<<(E_ + 31) / 32, 256>>>(edge_attr, src, batch);

    // layer 0 aggregation (collect BN stats)
    agg_kernel<<<(N_ + 7) / 8, 256>>>(0, x, h_ptr, bias, 1);
    bn_norm_kernel<<<(N_ * 64 + 255) / 256, 256>>>(h_ptr, bn_gamma, bn_beta);

    // layer 1
    gemm_xl<<<(N_ + 63) / 64, 256, GEMM_SHM>>>(h_ptr, W_l + 128 * 128, instr + B_ * 64, batch);
    alr_kernel<<<(N_ + 7) / 8, 256>>>(h_ptr, batch, 1);
    agg_kernel<<<(N_ + 7) / 8, 256>>>(1, h_ptr, out, bias, 0);
}

// round 3
// speedup vs baseline: 1.4418x; 1.3289x over previous
#include <cuda_runtime.h>
#include <cuda_bf16.h>

#define N_   20000
#define E_   320000
#define B_   128
#define L_   2
#define SLOPE 0.2f
#define EPS_  1e-5f

// ---------------- scratch (static device allocations) ----------------
__device__ int   g_counts[N_];
__device__ int   g_rowptr[N_ + 1];
__device__ int   g_cursor[N_];
__device__ int   g_csr_src[E_];
__device__ int   g_perm[E_];

__device__ float g_wea[L_][128][2];   // collapsed W_e * att_e
__device__ float g_inse[L_][B_][2];   // ins part of ae per graph

__device__ float2 g_ae[L_][E_];       // edge attention term, CSR-permuted
__device__ float2 g_att[E_];          // scratch: post-leaky logits (per layer)
__device__ float g_xl[(size_t)N_ * 128];
__device__ float g_alr[N_ * 4];       // al0, al1, ar0, ar1
__device__ float g_h[(size_t)N_ * 64];
__device__ float g_bnstats[128];      // sum[64], sumsq[64]

// ---------------- CSR build ----------------
__global__ void zero_kernel() {
    int i = blockIdx.x * blockDim.x + threadIdx.x;
    if (i < N_) g_counts[i] = 0;
    if (i < 128) g_bnstats[i] = 0.f;
}

__global__ void hist_kernel(const int* __restrict__ dst) {
    int i = blockIdx.x * blockDim.x + threadIdx.x;
    if (i < E_) atomicAdd(&g_counts[dst[i]], 1);
}

// single block, 1024 threads, 20 elems per thread (serial) + one block scan
__global__ void scan_kernel() {
    __shared__ int sums[1024];
    const int C = 20;                  // 1024*20 = 20480 >= N_
    int t = threadIdx.x;
    int base = t * C;
    int vals[C];
    int run = 0;
    #pragma unroll
    for (int i = 0; i < C; i++) {
        int idx = base + i;
        int v = (idx < N_) ? g_counts[idx] : 0;
        run += v;
        vals[i] = run;                 // thread-local inclusive
    }
    sums[t] = run;
    __syncthreads();
    for (int o = 1; o < 1024; o <<= 1) {
        int x = (t >= o) ? sums[t - o] : 0;
        __syncthreads();
        sums[t] += x;
        __syncthreads();
    }
    int off = sums[t] - run;           // exclusive prefix of this thread's chunk
    if (t == 0) g_rowptr[0] = 0;
    #pragma unroll
    for (int i = 0; i < C; i++) {
        int idx = base + i;
        if (idx < N_) {
            int incl = off + vals[i];
            int cnt  = vals[i] - (i ? vals[i - 1] : 0);
            g_rowptr[idx + 1] = incl;
            g_cursor[idx]     = incl - cnt;
        }
    }
}

__global__ void scatter_kernel(const int* __restrict__ src, const int* __restrict__ dst) {
    int i = blockIdx.x * blockDim.x + threadIdx.x;
    if (i < E_) {
        int d = dst[i];
        int pos = atomicAdd(&g_cursor[d], 1);
        g_csr_src[pos] = src[i];
        g_perm[i] = pos;
    }
}

// ---------------- setup: collapse W_e*att_e + edge ins dots (edge path only) ----------------
__global__ void setup_kernel(const float* __restrict__ W_e,
                             const float* __restrict__ att_e,
                             const float* __restrict__ instr) {
    int tid = threadIdx.x;             // 256 threads, 1 block
    for (int idx = tid; idx < L_ * 128 * 2; idx += 256) {
        int l = idx >> 8;
        int k = (idx >> 1) & 127;
        int h = idx & 1;
        const float* wrow = W_e + ((size_t)l * 128 + k) * 128 + h * 64;
        const float* arow = att_e + l * 128 + h * 64;
        float s = 0.f;
        #pragma unroll 8
        for (int c = 0; c < 64; c++) s += wrow[c] * arow[c];
        g_wea[l][k][h] = s;
    }
    __syncthreads();
    for (int idx = tid; idx < L_ * B_ * 2; idx += 256) {
        int l = idx >> 8;
        int b = (idx >> 1) & 127;
        int h = idx & 1;
        const float* iv = instr + ((size_t)l * B_ + b) * 64;
        float s = 0.f;
        #pragma unroll 8
        for (int k = 0; k < 64; k++) s += iv[k] * g_wea[l][64 + k][h];
        g_inse[l][b][h] = s;
    }
}

// ---------------- ae: both layers, 4 edges per warp, grid-stride persistent ----------------
__global__ void ae_kernel(const float* __restrict__ edge_attr,
                          const int* __restrict__ srcv,
                          const int* __restrict__ batch) {
    __shared__ float swe[L_][64][2];
    int tid = threadIdx.x;
    for (int i = tid; i < L_ * 64 * 2; i += 256) {
        int l = i >> 7, rem = i & 127;
        swe[l][rem >> 1][rem & 1] = g_wea[l][rem >> 1][rem & 1];
    }
    __syncthreads();
    int lane = tid & 31;
    int sub = lane >> 3, l8 = lane & 7;
    int nwarps = gridDim.x * 8;
    for (int warp = blockIdx.x * 8 + (tid >> 5); warp < E_ / 4; warp += nwarps) {
        int e = warp * 4 + sub;
        const float* row = edge_attr + (size_t)e * 64;
        float4 v0 = *(const float4*)(row + l8 * 4);
        float4 v1 = *(const float4*)(row + 32 + l8 * 4);
        float vv[8] = {v0.x, v0.y, v0.z, v0.w, v1.x, v1.y, v1.z, v1.w};
        int k0 = l8 * 4;
        float acc[4] = {0.f, 0.f, 0.f, 0.f};
        #pragma unroll
        for (int j = 0; j < 8; j++) {
            int k = (j < 4) ? (k0 + j) : (32 + k0 + j - 4);
            #pragma unroll
            for (int l = 0; l < 2; l++)
                #pragma unroll
                for (int h = 0; h < 2; h++)
                    acc[l * 2 + h] += vv[j] * swe[l][k][h];
        }
        #pragma unroll
        for (int o = 4; o; o >>= 1) {
            #pragma unroll
            for (int c = 0; c < 4; c++)
                acc[c] += __shfl_xor_sync(0xffffffffu, acc[c], o);
        }
        if (l8 == 0) {
            int b = batch[srcv[e]];
            int pos = g_perm[e];
            g_ae[0][pos] = make_float2(acc[0] + g_inse[0][b][0], acc[1] + g_inse[0][b][1]);
            g_ae[1][pos] = make_float2(acc[2] + g_inse[1][b][0], acc[3] + g_inse[1][b][1]);
        }
    }
}

// ---------------- xl GEMM with fused alr epilogue and optional fused BN on input ----------------
#define GEMM_SHM ((128 * 68 + 128 * 128) * 4)
__global__ void gemm_xl(const float* __restrict__ hin,
                        const float* __restrict__ Wl,
                        const float* __restrict__ ins,
                        const int* __restrict__ batch,
                        const float* __restrict__ attL,
                        const float* __restrict__ attR,
                        int bn,
                        const float* __restrict__ gamma,
                        const float* __restrict__ beta) {
    extern __shared__ float sh[];
    float* As = sh;                 // [128][68], k-major (transposed)
    float* Ws = sh + 128 * 68;      // [128][128], k-major
    __shared__ int   sbatch[64];
    __shared__ float s_sc[64], s_sh[64];
    int tid = threadIdx.x;
    int node0 = blockIdx.x * 64;
    int rows = min(64, N_ - node0);
    if (tid < 64) sbatch[tid] = (tid < rows) ? batch[node0 + tid] : 0;
    if (bn && tid >= 64 && tid < 128) {
        int c = tid - 64;
        float mu  = g_bnstats[c] * (1.f / N_);
        float var = g_bnstats[64 + c] * (1.f / N_) - mu * mu;
        float inv = rsqrtf(var + EPS_);
        float sc = inv * gamma[c];
        s_sc[c] = sc;
        s_sh[c] = beta[c] - mu * sc;
    }
    const float4* Wg = (const float4*)Wl;
    float4* Ws4 = (float4*)Ws;
    for (int i = tid; i < 128 * 32; i += 256) Ws4[i] = Wg[i];
    __syncthreads();
    for (int i = tid; i < 64 * 128; i += 256) {
        int m = i >> 7, k = i & 127;
        float v = 0.f;
        if (m < rows) {
            if (k < 64) {
                v = hin[(size_t)(node0 + m) * 64 + k];
                if (bn) { v = v * s_sc[k] + s_sh[k]; v = v > 0.f ? v : 0.f; }
            } else {
                v = ins[(size_t)sbatch[m] * 64 + (k - 64)];
            }
        }
        As[k * 68 + m] = v;
    }
    __syncthreads();
    int rt = tid >> 5, lane = tid & 31;
    float acc[8][4];
    #pragma unroll
    for (int r = 0; r < 8; r++)
        #pragma unroll
        for (int j = 0; j < 4; j++) acc[r][j] = 0.f;
    #pragma unroll 4
    for (int k = 0; k < 128; k++) {
        const float* ar = As + k * 68 + rt * 8;
        float4 a0 = *(const float4*)ar;
        float4 a1 = *(const float4*)(ar + 4);
        float4 b  = *(const float4*)(Ws + k * 128 + lane * 4);
        float av[8] = {a0.x, a0.y, a0.z, a0.w, a1.x, a1.y, a1.z, a1.w};
        #pragma unroll
        for (int r = 0; r < 8; r++) {
            acc[r][0] += av[r] * b.x;
            acc[r][1] += av[r] * b.y;
            acc[r][2] += av[r] * b.z;
            acc[r][3] += av[r] * b.w;
        }
    }
    #pragma unroll
    for (int r = 0; r < 8; r++) {
        int m = rt * 8 + r;
        if (m < rows) {
            float4 v = {acc[r][0], acc[r][1], acc[r][2], acc[r][3]};
            *(float4*)(g_xl + (size_t)(node0 + m) * 128 + lane * 4) = v;
        }
    }
    // fused alr epilogue: al = xl . att_l, ar = xl . att_r (ins part already inside xl)
    float4 atl = *(const float4*)(attL + lane * 4);
    float4 atr = *(const float4*)(attR + lane * 4);
    #pragma unroll
    for (int r = 0; r < 8; r++) {
        float pl = acc[r][0] * atl.x + acc[r][1] * atl.y + acc[r][2] * atl.z + acc[r][3] * atl.w;
        float pr = acc[r][0] * atr.x + acc[r][1] * atr.y + acc[r][2] * atr.z + acc[r][3] * atr.w;
        #pragma unroll
        for (int o = 8; o; o >>= 1) {
            pl += __shfl_xor_sync(0xffffffffu, pl, o);
            pr += __shfl_xor_sync(0xffffffffu, pr, o);
        }
        // lanes 0-15 hold head0 sums, 16-31 head1 sums
        float pl1 = __shfl_sync(0xffffffffu, pl, 16);
        float pr1 = __shfl_sync(0xffffffffu, pr, 16);
        int m = rt * 8 + r;
        if (lane == 0 && m < rows) {
            float4 v = {pl, pl1, pr, pr1};
            *(float4*)(g_alr + (size_t)(node0 + m) * 4) = v;
        }
    }
}

// ---------------- per-node online softmax + aggregation; grid-stride warps ----------------
__global__ void agg_kernel(int layer, const float* __restrict__ hin,
                           float* __restrict__ hout,
                           const float* __restrict__ bias, int do_stats,
                           int bn_resid,
                           const float* __restrict__ gamma,
                           const float* __restrict__ beta) {
    __shared__ float s_sum[64], s_sq[64], s_sc[64], s_sh[64];
    int tid = threadIdx.x;
    if (do_stats && tid < 64) { s_sum[tid] = 0.f; s_sq[tid] = 0.f; }
    if (bn_resid && tid < 64) {
        float mu  = g_bnstats[tid] * (1.f / N_);
        float var = g_bnstats[64 + tid] * (1.f / N_) - mu * mu;
        float inv = rsqrtf(var + EPS_);
        float sc = inv * gamma[tid];
        s_sc[tid] = sc;
        s_sh[tid] = beta[tid] - mu * sc;
    }
    __syncthreads();
    int lane = tid & 31;
    bool head1 = lane >= 16;
    int coff = lane * 4;               // only meaningful for lanes 0-15
    const float2* aep = g_ae[layer];
    const float* bz = bias + layer * 64;
    int nwarps = gridDim.x * 8;
    for (int node = blockIdx.x * 8 + (tid >> 5); node < N_; node += nwarps) {
        int start = g_rowptr[node], end = g_rowptr[node + 1];
        float2 arr = *(const float2*)&g_alr[node * 4 + 2];
        // pass A: online (max, sum) + store post-leaky logits
        float m0 = -1e30f, m1 = -1e30f, s0 = 0.f, s1 = 0.f;
        for (int p = start + lane; p < end; p += 32) {
            int s = g_csr_src[p];
            float2 al = *(const float2*)&g_alr[s * 4];
            float2 ae = aep[p];
            float a0 = al.x + arr.x + ae.x; a0 = fmaxf(a0, SLOPE * a0);
            float a1 = al.y + arr.y + ae.y; a1 = fmaxf(a1, SLOPE * a1);
            g_att[p] = make_float2(a0, a1);
            float nm0 = fmaxf(m0, a0);
            s0 = s0 * __expf(m0 - nm0) + __expf(a0 - nm0); m0 = nm0;
            float nm1 = fmaxf(m1, a1);
            s1 = s1 * __expf(m1 - nm1) + __expf(a1 - nm1); m1 = nm1;
        }
        #pragma unroll
        for (int o = 16; o; o >>= 1) {
            float om0 = __shfl_xor_sync(0xffffffffu, m0, o);
            float os0 = __shfl_xor_sync(0xffffffffu, s0, o);
            float nm0 = fmaxf(m0, om0);
            s0 = s0 * __expf(m0 - nm0) + os0 * __expf(om0 - nm0); m0 = nm0;
            float om1 = __shfl_xor_sync(0xffffffffu, m1, o);
            float os1 = __shfl_xor_sync(0xffffffffu, s1, o);
            float nm1 = fmaxf(m1, om1);
            s1 = s1 * __expf(m1 - nm1) + os1 * __expf(om1 - nm1); m1 = nm1;
        }
        float sc0 = 1.f / (s0 + 1e-16f), sc1 = 1.f / (s1 + 1e-16f);
        __threadfence_block();
        __syncwarp();
        // pass B: weighted aggregation, unrolled x4 for MLP
        float mh = head1 ? m1 : m0;
        float acc0 = 0.f, acc1 = 0.f, acc2 = 0.f, acc3 = 0.f;
        int p = start;
        for (; p + 3 < end; p += 4) {
            int sA = g_csr_src[p],     sB = g_csr_src[p + 1];
            int sC = g_csr_src[p + 2], sD = g_csr_src[p + 3];
            float2 aA = g_att[p],     aB = g_att[p + 1];
            float2 aC = g_att[p + 2], aD = g_att[p + 3];
            float4 xA = *(const float4*)(g_xl + (size_t)sA * 128 + coff + (head1 ? 0 : 0) + lane * 0 + (tid & 31) * 4 - coff);
            // (the above reduces to g_xl + sA*128 + lane*4; written explicitly below)
            xA = *(const float4*)(g_xl + (size_t)sA * 128 + (tid & 31) * 4);
            float4 xB = *(const float4*)(g_xl + (size_t)sB * 128 + (tid & 31) * 4);
            float4 xC = *(const float4*)(g_xl + (size_t)sC * 128 + (tid & 31) * 4);
            float4 xD = *(const float4*)(g_xl + (size_t)sD * 128 + (tid & 31) * 4);
            float wA = __expf((head1 ? aA.y : aA.x) - mh);
            float wB = __expf((head1 ? aB.y : aB.x) - mh);
            float wC = __expf((head1 ? aC.y : aC.x) - mh);
            float wD = __expf((head1 ? aD.y : aD.x) - mh);
            acc0 += wA * xA.x + wB * xB.x + wC * xC.x + wD * xD.x;
            acc1 += wA * xA.y + wB * xB.y + wC * xC.y + wD * xD.y;
            acc2 += wA * xA.z + wB * xB.z + wC * xC.z + wD * xD.z;
            acc3 += wA * xA.w + wB * xB.w + wC * xC.w + wD * xD.w;
        }
        for (; p < end; p++) {
            int s = g_csr_src[p];
            float2 a = g_att[p];
            float w = __expf((head1 ? a.y : a.x) - mh);
            float4 x = *(const float4*)(g_xl + (size_t)s * 128 + (tid & 31) * 4);
            acc0 += w * x.x; acc1 += w * x.y; acc2 += w * x.z; acc3 += w * x.w;
        }
        float sc = head1 ? sc1 : sc0;
        float o0 = acc0 * sc, o1 = acc1 * sc, o2 = acc2 * sc, o3 = acc3 * sc;
        float p0 = __shfl_xor_sync(0xffffffffu, o0, 16);
        float p1 = __shfl_xor_sync(0xffffffffu, o1, 16);
        float p2 = __shfl_xor_sync(0xffffffffu, o2, 16);
        float p3 = __shfl_xor_sync(0xffffffffu, o3, 16);
        if (!head1) {
            float4 hv = *(const float4*)(hin + (size_t)node * 64 + coff);
            if (bn_resid) {
                hv.x = fmaxf(hv.x * s_sc[coff + 0] + s_sh[coff + 0], 0.f);
                hv.y = fmaxf(hv.y * s_sc[coff + 1] + s_sh[coff + 1], 0.f);
                hv.z = fmaxf(hv.z * s_sc[coff + 2] + s_sh[coff + 2], 0.f);
                hv.w = fmaxf(hv.w * s_sc[coff + 3] + s_sh[coff + 3], 0.f);
            }
            float4 bv = *(const float4*)(bz + coff);
            float r0 = (o0 + p0) * 0.5f + bv.x + hv.x;
            float r1 = (o1 + p1) * 0.5f + bv.y + hv.y;
            float r2 = (o2 + p2) * 0.5f + bv.z + hv.z;
            float r3 = (o3 + p3) * 0.5f + bv.w + hv.w;
            float4 res = {r0, r1, r2, r3};
            *(float4*)(hout + (size_t)node * 64 + coff) = res;
            if (do_stats) {
                atomicAdd(&s_sum[coff + 0], r0); atomicAdd(&s_sq[coff + 0], r0 * r0);
                atomicAdd(&s_sum[coff + 1], r1); atomicAdd(&s_sq[coff + 1], r1 * r1);
                atomicAdd(&s_sum[coff + 2], r2); atomicAdd(&s_sq[coff + 2], r2 * r2);
                atomicAdd(&s_sum[coff + 3], r3); atomicAdd(&s_sq[coff + 3], r3 * r3);
            }
        }
    }
    if (do_stats) {
        __syncthreads();
        if (tid < 64) {
            atomicAdd(&g_bnstats[tid],      s_sum[tid]);
            atomicAdd(&g_bnstats[64 + tid], s_sq[tid]);
        }
    }
}

// ---------------- launch ----------------
extern "C" void kernel_launch(void* const* d_in, const int* in_sizes, int n_in,
                              void* d_out, int out_size) {
    const float* x         = (const float*)d_in[0];
    const int*   eidx      = (const int*)d_in[1];
    const float* edge_attr = (const float*)d_in[2];
    const float* instr     = (const float*)d_in[3];
    const int*   batch     = (const int*)d_in[4];
    const float* W_l       = (const float*)d_in[5];
    const float* W_e       = (const float*)d_in[6];
    const float* att_l     = (const float*)d_in[7];
    const float* att_r     = (const float*)d_in[8];
    const float* att_e     = (const float*)d_in[9];
    const float* bias      = (const float*)d_in[10];
    const float* bn_gamma  = (const float*)d_in[11];
    const float* bn_beta   = (const float*)d_in[12];
    float* out = (float*)d_out;

    const int* src = eidx;
    const int* dst = eidx + E_;

    float* h_ptr = nullptr;
    cudaGetSymbolAddress((void**)&h_ptr, g_h);
    cudaFuncSetAttribute(gemm_xl, cudaFuncAttributeMaxDynamicSharedMemorySize, GEMM_SHM);

    // fork-join: CSR build on a side stream, overlapped with gemm0 + setup
    cudaStream_t s2;
    cudaStreamCreateWithFlags(&s2, cudaStreamNonBlocking);
    cudaEvent_t e1, e2;
    cudaEventCreateWithFlags(&e1, cudaEventDisableTiming);
    cudaEventCreateWithFlags(&e2, cudaEventDisableTiming);

    cudaEventRecord(e1, 0);
    cudaStreamWaitEvent(s2, e1, 0);
    zero_kernel<<<(N_ + 255) / 256, 256, 0, s2>>>();
    hist_kernel<<<(E_ + 255) / 256, 256, 0, s2>>>(dst);
    scan_kernel<<<1, 1024, 0, s2>>>();
    scatter_kernel<<<(E_ + 255) / 256, 256, 0, s2>>>(src, dst);
    cudaEventRecord(e2, s2);

    // main stream: layer-0 GEMM (independent of CSR and setup), then edge-weight setup
    gemm_xl<<<(N_ + 63) / 64, 256, GEMM_SHM>>>(x, W_l, instr, batch,
                                               att_l, att_r, 0, nullptr, nullptr);
    setup_kernel<<<1, 256>>>(W_e, att_e, instr);

    cudaStreamWaitEvent(0, e2, 0);     // join CSR branch
    ae_kernel<<<592, 256>>>(edge_attr, src, batch);

    // layer 0 aggregation (collect BN stats, no BN on residual)
    agg_kernel<<<1280, 256>>>(0, x, h_ptr, bias, 1, 0, nullptr, nullptr);

    // layer 1: GEMM with BN+relu fused on input, agg with BN+relu fused on residual
    gemm_xl<<<(N_ + 63) / 64, 256, GEMM_SHM>>>(h_ptr, W_l + 128 * 128, instr + B_ * 64, batch,
                                               att_l + 128, att_r + 128, 1, bn_gamma, bn_beta);
    agg_kernel<<<1280, 256>>>(1, h_ptr, out, bias, 0, 1, bn_gamma, bn_beta);
}